// round 2
// baseline (speedup 1.0000x reference)
#include <cuda_runtime.h>

// ChebyshevEncoder: x*scale -> Chebyshev T0..T7 -> per-(h,i) 8x8 matmul -> *poly
// -> silu -> flatten [b, h*i*k] -> LayerNorm over 16384 features.
//
// Two-kernel recompute scheme:
//   k_stats: per-(rowblock, iblock) CTA computes silu values, accumulates per-row
//            sum/sumsq partials into __device__ scratch (weights live in registers,
//            reused across 32 rows -> kernels L2 traffic ~64MB instead of 2GB).
//   k_out:   reduces the 8 partials per row -> mean/rstd, recomputes silu, writes
//            normalized output with float4 stores.
// Dot products use packed fma.rn.f32x2 (FFMA2) to halve fma-pipe issue pressure.
// Thread mapping: h = tid>>6, il = tid&63 -> each warp covers 32 consecutive i at
// fixed h: coalesced x loads (128B/warp) and contiguous 1KB store span in k_out.

#define B_    4096
#define I_    512
#define M_    8
#define H_    4
#define K_    8
#define F_    16384      // H_*I_*K_
#define FB_   8          // feature (i) blocks
#define IC_   64         // i per block  (FB_*IC_ == I_)
#define RB_   32         // rows per CTA
#define RBLK_ 128        // row blocks   (RB_*RBLK_ == B_)
#define NT_   256        // threads: (h 0..3) x (il 0..63)
#define LNEPS 1e-5f

// per-row, per-featureblock partial [sum, sumsq]
__device__ float g_part[B_][FB_][2];

static __device__ __forceinline__ unsigned long long pack2(float lo, float hi) {
    unsigned long long r;
    asm("mov.b64 %0, {%1, %2};" : "=l"(r) : "f"(lo), "f"(hi));
    return r;
}
static __device__ __forceinline__ void unpack2(unsigned long long v, float& lo, float& hi) {
    asm("mov.b64 {%0, %1}, %2;" : "=f"(lo), "=f"(hi) : "l"(v));
}
static __device__ __forceinline__ unsigned long long ffma2(
        unsigned long long a, unsigned long long b, unsigned long long c) {
    unsigned long long d;
    asm("fma.rn.f32x2 %0, %1, %2, %3;" : "=l"(d) : "l"(a), "l"(b), "l"(c));
    return d;
}

// silu(z) = z / (1 + exp(-z)); exp overflow/underflow limits behave correctly:
//   z >> 0: e->0 -> z ;  z << 0: e->inf -> z*rcp(inf) = -0 ~= 0.
static __device__ __forceinline__ float silu_f(float z) {
    float e = __expf(-z);
    return __fdividef(z, 1.0f + e);
}

// Load this thread's 8x8 weight slice (poly pre-folded) as 32 packed f32x2 regs.
static __device__ __forceinline__ void load_weights(
        const float* __restrict__ kern, const float* __restrict__ poly,
        int h, int i, unsigned long long* w2) {
    const float4* wq = reinterpret_cast<const float4*>(kern + (size_t)(h * I_ + i) * (M_ * K_));
    const float4* pq = reinterpret_cast<const float4*>(poly + (size_t)(h * I_ + i) * K_);
    float4 p0 = pq[0], p1 = pq[1];
#pragma unroll
    for (int m = 0; m < M_; m++) {
        float4 a = wq[2 * m], b = wq[2 * m + 1];
        w2[4 * m + 0] = pack2(a.x * p0.x, a.y * p0.y);
        w2[4 * m + 1] = pack2(a.z * p0.z, a.w * p0.w);
        w2[4 * m + 2] = pack2(b.x * p1.x, b.y * p1.y);
        w2[4 * m + 3] = pack2(b.z * p1.z, b.w * p1.w);
    }
}

// Chebyshev recurrence + packed 8-term dot -> z[0..7] (pre-silu activations).
static __device__ __forceinline__ void compute_z(
        float xs, const unsigned long long* w2, float* z) {
    float c[M_];
    c[0] = 1.0f;
    c[1] = xs;
    float t2 = xs + xs;
#pragma unroll
    for (int n = 2; n < M_; n++) c[n] = fmaf(t2, c[n - 1], -c[n - 2]);

    unsigned long long a0 = w2[0], a1 = w2[1], a2 = w2[2], a3 = w2[3];  // c[0]==1
#pragma unroll
    for (int m = 1; m < M_; m++) {
        unsigned long long cm = pack2(c[m], c[m]);
        a0 = ffma2(cm, w2[4 * m + 0], a0);
        a1 = ffma2(cm, w2[4 * m + 1], a1);
        a2 = ffma2(cm, w2[4 * m + 2], a2);
        a3 = ffma2(cm, w2[4 * m + 3], a3);
    }
    unpack2(a0, z[0], z[1]);
    unpack2(a1, z[2], z[3]);
    unpack2(a2, z[4], z[5]);
    unpack2(a3, z[6], z[7]);
}

__global__ void __launch_bounds__(NT_) k_stats(
        const float* __restrict__ x, const float* __restrict__ scale,
        const float* __restrict__ poly, const float* __restrict__ kern) {
    __shared__ float wacc[RB_][8][2];  // per-row, per-warp partials

    int tid = threadIdx.x;
    int h = tid >> 6, il = tid & 63;       // warp = 32 consecutive il at fixed h
    int fb = blockIdx.y;
    int i = fb * IC_ + il;
    int row0 = blockIdx.x * RB_;
    int wid = tid >> 5, lane = tid & 31;

    unsigned long long w2[32];
    load_weights(kern, poly, h, i, w2);
    float si = scale[i];

    const float* xrow = x + (size_t)row0 * I_ + i;

#pragma unroll 1
    for (int r = 0; r < RB_; r++) {
        float xs = xrow[(size_t)r * I_] * si;
        float z[8];
        compute_z(xs, w2, z);
        float sum = 0.0f, sq = 0.0f;
#pragma unroll
        for (int k = 0; k < 8; k++) {
            float s = silu_f(z[k]);
            sum += s;
            sq = fmaf(s, s, sq);
        }
#pragma unroll
        for (int off = 16; off; off >>= 1) {
            sum += __shfl_xor_sync(0xffffffffu, sum, off);
            sq  += __shfl_xor_sync(0xffffffffu, sq, off);
        }
        if (lane == 0) {
            wacc[r][wid][0] = sum;
            wacc[r][wid][1] = sq;
        }
    }
    __syncthreads();
    if (tid < RB_ * 2) {
        int r = tid >> 1, comp = tid & 1;
        float v = 0.0f;
#pragma unroll
        for (int w = 0; w < 8; w++) v += wacc[r][w][comp];
        g_part[row0 + r][fb][comp] = v;
    }
}

__global__ void __launch_bounds__(NT_) k_out(
        const float* __restrict__ x, const float* __restrict__ scale,
        const float* __restrict__ poly, const float* __restrict__ kern,
        const float* __restrict__ gamma, const float* __restrict__ beta,
        float* __restrict__ out) {
    __shared__ float srow[RB_][2];  // mean, rstd per row

    int tid = threadIdx.x;
    int h = tid >> 6, il = tid & 63;
    int fb = blockIdx.y;
    int i = fb * IC_ + il;
    int row0 = blockIdx.x * RB_;

    if (tid < RB_) {
        float sum = 0.0f, sq = 0.0f;
#pragma unroll
        for (int f = 0; f < FB_; f++) {
            sum += g_part[row0 + tid][f][0];
            sq  += g_part[row0 + tid][f][1];
        }
        float mean = sum * (1.0f / F_);
        float var = fmaf(-mean, mean, sq * (1.0f / F_));  // biased variance
        srow[tid][0] = mean;
        srow[tid][1] = rsqrtf(var + LNEPS);
    }

    unsigned long long w2[32];
    load_weights(kern, poly, h, i, w2);
    float si = scale[i];

    int fbase = h * (I_ * K_) + i * K_;
    const float4* gq = reinterpret_cast<const float4*>(gamma + fbase);
    const float4* bq = reinterpret_cast<const float4*>(beta + fbase);
    float4 g0 = gq[0], g1 = gq[1], b0 = bq[0], b1 = bq[1];

    __syncthreads();

    const float* xrow = x + (size_t)row0 * I_ + i;
    float4* orow = reinterpret_cast<float4*>(out + (size_t)row0 * F_ + fbase);

#pragma unroll 1
    for (int r = 0; r < RB_; r++) {
        float mean = srow[r][0], rstd = srow[r][1];
        float xs = xrow[(size_t)r * I_] * si;
        float z[8];
        compute_z(xs, w2, z);
        float s[8];
#pragma unroll
        for (int k = 0; k < 8; k++) s[k] = (silu_f(z[k]) - mean) * rstd;

        float4 o0, o1;
        o0.x = fmaf(s[0], g0.x, b0.x);
        o0.y = fmaf(s[1], g0.y, b0.y);
        o0.z = fmaf(s[2], g0.z, b0.z);
        o0.w = fmaf(s[3], g0.w, b0.w);
        o1.x = fmaf(s[4], g1.x, b1.x);
        o1.y = fmaf(s[5], g1.y, b1.y);
        o1.z = fmaf(s[6], g1.z, b1.z);
        o1.w = fmaf(s[7], g1.w, b1.w);

        float4* op = orow + (size_t)r * (F_ / 4);
        op[0] = o0;
        op[1] = o1;
    }
}

extern "C" void kernel_launch(void* const* d_in, const int* in_sizes, int n_in,
                              void* d_out, int out_size) {
    const float* x     = (const float*)d_in[0];
    const float* scale = (const float*)d_in[1];
    const float* poly  = (const float*)d_in[2];
    const float* kern  = (const float*)d_in[3];
    const float* gamma = (const float*)d_in[4];
    const float* beta  = (const float*)d_in[5];
    float* out = (float*)d_out;

    dim3 grid(RBLK_, FB_);
    k_stats<<<grid, NT_>>>(x, scale, poly, kern);
    k_out<<<grid, NT_>>>(x, scale, poly, kern, gamma, beta, out);
}

// round 8
// speedup vs baseline: 1.3194x; 1.3194x over previous
#include <cuda_runtime.h>

// ChebyshevEncoder: x*scale -> Chebyshev T0..T7 -> per-(h,i) 8x8 matmul -> *poly
// -> silu -> flatten [b, h*i*k] -> LayerNorm over 16384 features.
//
// Two-kernel recompute scheme. k-split: each thread owns 4 outputs (one k-half)
// -> 32 weight regs instead of 64 -> ~75 regs/thread -> 3 CTAs/SM (24 warps) vs
// the R2-measured baseline (regs=111, occ 23.2%, issue 26.9%, latency-bound).
// Warp = 32 consecutive i at fixed (h, k-half): coalesced x loads.
// Next-row x value is prefetched to hide L2 latency.
// Grid is fb-major: concurrently-resident CTAs share weight cache lines in L2.
//
// R5 fix (kept): compute_z_half sets c[0] = 1.0f (read by the Chebyshev
// recurrence); its omission caused the R4 NaN failure.
// R7 == R6 == R5 byte-identical re-land after broker timeouts.

#define B_    4096
#define I_    512
#define M_    8
#define H_    4
#define K_    8
#define F_    16384      // H_*I_*K_
#define FB_   16         // feature (i) blocks
#define IC_   32         // i per block  (FB_*IC_ == I_)
#define RB_   32         // rows per CTA
#define RBLK_ 128        // row blocks   (RB_*RBLK_ == B_)
#define NT_   256        // threads: kh(2) x h(4) x il(32)
#define LNEPS 1e-5f

// per-row, per-featureblock partial [sum, sumsq]
__device__ float g_part[B_][FB_][2];

static __device__ __forceinline__ unsigned long long pack2(float lo, float hi) {
    unsigned long long r;
    asm("mov.b64 %0, {%1, %2};" : "=l"(r) : "f"(lo), "f"(hi));
    return r;
}
static __device__ __forceinline__ void unpack2(unsigned long long v, float& lo, float& hi) {
    asm("mov.b64 {%0, %1}, %2;" : "=f"(lo), "=f"(hi) : "l"(v));
}
static __device__ __forceinline__ unsigned long long ffma2(
        unsigned long long a, unsigned long long b, unsigned long long c) {
    unsigned long long d;
    asm("fma.rn.f32x2 %0, %1, %2, %3;" : "=l"(d) : "l"(a), "l"(b), "l"(c));
    return d;
}

// silu(z) = z / (1 + exp(-z)); exp limits behave correctly at +-inf.
// (tanh.approx variant rejected: projected rel_err ~1e-3, too close to threshold.)
static __device__ __forceinline__ float silu_f(float z) {
    float e = __expf(-z);
    return __fdividef(z, 1.0f + e);
}

// Load this thread's 8x4 weight half-slice (poly pre-folded) as 16 packed f32x2.
static __device__ __forceinline__ void load_weights_half(
        const float* __restrict__ kern, const float* __restrict__ poly,
        int h, int i, int kh, unsigned long long* w2) {
    const float* wbase = kern + ((size_t)(h * I_ + i) * M_) * K_ + kh * 4;
    const float4 p = *reinterpret_cast<const float4*>(
        poly + (size_t)(h * I_ + i) * K_ + kh * 4);
#pragma unroll
    for (int m = 0; m < M_; m++) {
        float4 a = *reinterpret_cast<const float4*>(wbase + (size_t)m * K_);
        w2[2 * m + 0] = pack2(a.x * p.x, a.y * p.y);
        w2[2 * m + 1] = pack2(a.z * p.z, a.w * p.w);
    }
}

// Chebyshev recurrence + packed 4-term-wide dot -> z[0..3].
static __device__ __forceinline__ void compute_z_half(
        float xs, const unsigned long long* w2, float* z) {
    float c[M_];
    c[0] = 1.0f;                       // recurrence reads c[0]
    c[1] = xs;
    float t2 = xs + xs;
#pragma unroll
    for (int n = 2; n < M_; n++) c[n] = fmaf(t2, c[n - 1], -c[n - 2]);

    unsigned long long a0 = w2[0], a1 = w2[1];  // m=0 term: c[0]==1, so init = w2
#pragma unroll
    for (int m = 1; m < M_; m++) {
        unsigned long long cm = pack2(c[m], c[m]);
        a0 = ffma2(cm, w2[2 * m + 0], a0);
        a1 = ffma2(cm, w2[2 * m + 1], a1);
    }
    unpack2(a0, z[0], z[1]);
    unpack2(a1, z[2], z[3]);
}

__global__ void __launch_bounds__(NT_, 3) k_stats(
        const float* __restrict__ x, const float* __restrict__ scale,
        const float* __restrict__ poly, const float* __restrict__ kern) {
    __shared__ float wacc[RB_][8][2];  // per-row, per-warp partials

    int tid = threadIdx.x;
    int kh = tid >> 7, h = (tid >> 5) & 3, il = tid & 31;
    int fb = blockIdx.x;               // fb-major grid
    int i = fb * IC_ + il;
    int row0 = blockIdx.y * RB_;
    int wid = tid >> 5, lane = tid & 31;

    unsigned long long w2[16];
    load_weights_half(kern, poly, h, i, kh, w2);
    float si = scale[i];

    const float* xrow = x + (size_t)row0 * I_ + i;
    float xv = xrow[0];

#pragma unroll 1
    for (int r = 0; r < RB_; r++) {
        int rn = (r + 1 < RB_) ? r + 1 : r;
        float xv_next = xrow[(size_t)rn * I_];   // prefetch next row
        float xs = xv * si;
        float z[4];
        compute_z_half(xs, w2, z);
        float sum = 0.0f, sq = 0.0f;
#pragma unroll
        for (int k = 0; k < 4; k++) {
            float s = silu_f(z[k]);
            sum += s;
            sq = fmaf(s, s, sq);
        }
#pragma unroll
        for (int off = 16; off; off >>= 1) {
            sum += __shfl_xor_sync(0xffffffffu, sum, off);
            sq  += __shfl_xor_sync(0xffffffffu, sq, off);
        }
        if (lane == 0) {
            wacc[r][wid][0] = sum;
            wacc[r][wid][1] = sq;
        }
        xv = xv_next;
    }
    __syncthreads();
    if (tid < RB_ * 2) {
        int r = tid >> 1, comp = tid & 1;
        float v = 0.0f;
#pragma unroll
        for (int w = 0; w < 8; w++) v += wacc[r][w][comp];
        g_part[row0 + r][fb][comp] = v;
    }
}

__global__ void __launch_bounds__(NT_, 3) k_out(
        const float* __restrict__ x, const float* __restrict__ scale,
        const float* __restrict__ poly, const float* __restrict__ kern,
        const float* __restrict__ gamma, const float* __restrict__ beta,
        float* __restrict__ out) {
    __shared__ float srow[RB_][2];  // mean, rstd per row

    int tid = threadIdx.x;
    int kh = tid >> 7, h = (tid >> 5) & 3, il = tid & 31;
    int fb = blockIdx.x;               // fb-major grid
    int i = fb * IC_ + il;
    int row0 = blockIdx.y * RB_;

    if (tid < RB_) {
        float sum = 0.0f, sq = 0.0f;
#pragma unroll
        for (int f = 0; f < FB_; f++) {
            sum += g_part[row0 + tid][f][0];
            sq  += g_part[row0 + tid][f][1];
        }
        float mean = sum * (1.0f / F_);
        float var = fmaf(-mean, mean, sq * (1.0f / F_));  // biased variance
        srow[tid][0] = mean;
        srow[tid][1] = rsqrtf(var + LNEPS);
    }

    unsigned long long w2[16];
    load_weights_half(kern, poly, h, i, kh, w2);
    float si = scale[i];

    int fbase = h * (I_ * K_) + i * K_ + kh * 4;
    const float4 g0 = *reinterpret_cast<const float4*>(gamma + fbase);
    const float4 b0 = *reinterpret_cast<const float4*>(beta + fbase);

    __syncthreads();

    const float* xrow = x + (size_t)row0 * I_ + i;
    float* obase = out + (size_t)row0 * F_ + fbase;
    float xv = xrow[0];

#pragma unroll 1
    for (int r = 0; r < RB_; r++) {
        int rn = (r + 1 < RB_) ? r + 1 : r;
        float xv_next = xrow[(size_t)rn * I_];   // prefetch next row
        float mean = srow[r][0], rstd = srow[r][1];
        float xs = xv * si;
        float z[4];
        compute_z_half(xs, w2, z);
        float s[4];
#pragma unroll
        for (int k = 0; k < 4; k++) s[k] = (silu_f(z[k]) - mean) * rstd;

        float4 o;
        o.x = fmaf(s[0], g0.x, b0.x);
        o.y = fmaf(s[1], g0.y, b0.y);
        o.z = fmaf(s[2], g0.z, b0.z);
        o.w = fmaf(s[3], g0.w, b0.w);
        *reinterpret_cast<float4*>(obase + (size_t)r * F_) = o;
        xv = xv_next;
    }
}

extern "C" void kernel_launch(void* const* d_in, const int* in_sizes, int n_in,
                              void* d_out, int out_size) {
    const float* x     = (const float*)d_in[0];
    const float* scale = (const float*)d_in[1];
    const float* poly  = (const float*)d_in[2];
    const float* kern  = (const float*)d_in[3];
    const float* gamma = (const float*)d_in[4];
    const float* beta  = (const float*)d_in[5];
    float* out = (float*)d_out;

    dim3 grid(FB_, RBLK_);
    k_stats<<<grid, NT_>>>(x, scale, poly, kern);
    k_out<<<grid, NT_>>>(x, scale, poly, kern, gamma, beta, out);
}

// round 12
// speedup vs baseline: 1.8187x; 1.3784x over previous
#include <cuda_runtime.h>

// ChebyshevEncoder: x*scale -> Chebyshev T0..T7 -> per-(h,i) 8x8 matmul -> *poly
// -> silu -> flatten [b, h*i*k] -> LayerNorm over 16384 features.
//
// Two-kernel recompute scheme + k-split (R8-measured: 175.4us, regs=78,
// occ 34.9%, issue 31.7%, L1 44.6% = top counter).
// R9 change (re-landed, byte-identical): lane remap kh=lane&1, isub=lane>>1 ->
// each warp's float4 stores are fully contiguous (512B span, no 32B-stride
// holes) -> halves L1 store wavefronts. Output stores use st.global.cs.

#define B_    4096
#define I_    512
#define M_    8
#define H_    4
#define K_    8
#define F_    16384      // H_*I_*K_
#define FB_   16         // feature (i) blocks
#define IC_   32         // i per block  (FB_*IC_ == I_)
#define RB_   32         // rows per CTA
#define RBLK_ 128        // row blocks   (RB_*RBLK_ == B_)
#define NT_   256        // 8 warps: warp=(h,ihalf), lane=(isub,kh)
#define LNEPS 1e-5f

// per-row, per-featureblock partial [sum, sumsq]
__device__ float g_part[B_][FB_][2];

static __device__ __forceinline__ unsigned long long pack2(float lo, float hi) {
    unsigned long long r;
    asm("mov.b64 %0, {%1, %2};" : "=l"(r) : "f"(lo), "f"(hi));
    return r;
}
static __device__ __forceinline__ void unpack2(unsigned long long v, float& lo, float& hi) {
    asm("mov.b64 {%0, %1}, %2;" : "=f"(lo), "=f"(hi) : "l"(v));
}
static __device__ __forceinline__ unsigned long long ffma2(
        unsigned long long a, unsigned long long b, unsigned long long c) {
    unsigned long long d;
    asm("fma.rn.f32x2 %0, %1, %2, %3;" : "=l"(d) : "l"(a), "l"(b), "l"(c));
    return d;
}

// silu(z) = z / (1 + exp(-z)); exp limits behave correctly at +-inf.
static __device__ __forceinline__ float silu_f(float z) {
    float e = __expf(-z);
    return __fdividef(z, 1.0f + e);
}

// Streaming 16B store (write-once output; evict-first in L2).
static __device__ __forceinline__ void stg_cs_128(float* p, float a, float b,
                                                  float c, float d) {
    asm volatile("st.global.cs.v4.f32 [%0], {%1, %2, %3, %4};"
                 :: "l"(p), "f"(a), "f"(b), "f"(c), "f"(d) : "memory");
}

// Load this thread's 8x4 weight half-slice (poly pre-folded) as 16 packed f32x2.
static __device__ __forceinline__ void load_weights_half(
        const float* __restrict__ kern, const float* __restrict__ poly,
        int h, int i, int kh, unsigned long long* w2) {
    const float* wbase = kern + ((size_t)(h * I_ + i) * M_) * K_ + kh * 4;
    const float4 p = *reinterpret_cast<const float4*>(
        poly + (size_t)(h * I_ + i) * K_ + kh * 4);
#pragma unroll
    for (int m = 0; m < M_; m++) {
        float4 a = *reinterpret_cast<const float4*>(wbase + (size_t)m * K_);
        w2[2 * m + 0] = pack2(a.x * p.x, a.y * p.y);
        w2[2 * m + 1] = pack2(a.z * p.z, a.w * p.w);
    }
}

// Chebyshev recurrence + packed 4-term-wide dot -> z[0..3].
static __device__ __forceinline__ void compute_z_half(
        float xs, const unsigned long long* w2, float* z) {
    float c[M_];
    c[0] = 1.0f;                       // recurrence reads c[0]
    c[1] = xs;
    float t2 = xs + xs;
#pragma unroll
    for (int n = 2; n < M_; n++) c[n] = fmaf(t2, c[n - 1], -c[n - 2]);

    unsigned long long a0 = w2[0], a1 = w2[1];  // m=0 term: c[0]==1, so init = w2
#pragma unroll
    for (int m = 1; m < M_; m++) {
        unsigned long long cm = pack2(c[m], c[m]);
        a0 = ffma2(cm, w2[2 * m + 0], a0);
        a1 = ffma2(cm, w2[2 * m + 1], a1);
    }
    unpack2(a0, z[0], z[1]);
    unpack2(a1, z[2], z[3]);
}

// Thread decomposition shared by both kernels:
//   warp w = tid>>5:  h = w>>1, ihalf = w&1
//   lane:             kh = lane&1, isub = lane>>1
//   i = fb*IC_ + ihalf*16 + isub
// -> k_out stores from consecutive lanes are contiguous 16B chunks.

__global__ void __launch_bounds__(NT_, 3) k_stats(
        const float* __restrict__ x, const float* __restrict__ scale,
        const float* __restrict__ poly, const float* __restrict__ kern) {
    __shared__ float wacc[RB_][8][2];  // per-row, per-warp partials

    int tid = threadIdx.x;
    int lane = tid & 31, wid = tid >> 5;
    int h = wid >> 1, ihalf = wid & 1;
    int kh = lane & 1, isub = lane >> 1;
    int fb = blockIdx.x;               // fb-major grid
    int i = fb * IC_ + ihalf * 16 + isub;
    int row0 = blockIdx.y * RB_;

    unsigned long long w2[16];
    load_weights_half(kern, poly, h, i, kh, w2);
    float si = scale[i];

    const float* xrow = x + (size_t)row0 * I_ + i;
    float xv = xrow[0];

#pragma unroll 1
    for (int r = 0; r < RB_; r++) {
        int rn = (r + 1 < RB_) ? r + 1 : r;
        float xv_next = xrow[(size_t)rn * I_];   // prefetch next row
        float xs = xv * si;
        float z[4];
        compute_z_half(xs, w2, z);
        float sum = 0.0f, sq = 0.0f;
#pragma unroll
        for (int k = 0; k < 4; k++) {
            float s = silu_f(z[k]);
            sum += s;
            sq = fmaf(s, s, sq);
        }
#pragma unroll
        for (int off = 16; off; off >>= 1) {
            sum += __shfl_xor_sync(0xffffffffu, sum, off);
            sq  += __shfl_xor_sync(0xffffffffu, sq, off);
        }
        if (lane == 0) {
            wacc[r][wid][0] = sum;
            wacc[r][wid][1] = sq;
        }
        xv = xv_next;
    }
    __syncthreads();
    if (tid < RB_ * 2) {
        int r = tid >> 1, comp = tid & 1;
        float v = 0.0f;
#pragma unroll
        for (int w = 0; w < 8; w++) v += wacc[r][w][comp];
        g_part[row0 + r][fb][comp] = v;
    }
}

__global__ void __launch_bounds__(NT_, 3) k_out(
        const float* __restrict__ x, const float* __restrict__ scale,
        const float* __restrict__ poly, const float* __restrict__ kern,
        const float* __restrict__ gamma, const float* __restrict__ beta,
        float* __restrict__ out) {
    __shared__ float srow[RB_][2];  // mean, rstd per row

    int tid = threadIdx.x;
    int lane = tid & 31, wid = tid >> 5;
    int h = wid >> 1, ihalf = wid & 1;
    int kh = lane & 1, isub = lane >> 1;
    int fb = blockIdx.x;               // fb-major grid
    int i = fb * IC_ + ihalf * 16 + isub;
    int row0 = blockIdx.y * RB_;

    if (tid < RB_) {
        float sum = 0.0f, sq = 0.0f;
#pragma unroll
        for (int f = 0; f < FB_; f++) {
            sum += g_part[row0 + tid][f][0];
            sq  += g_part[row0 + tid][f][1];
        }
        float mean = sum * (1.0f / F_);
        float var = fmaf(-mean, mean, sq * (1.0f / F_));  // biased variance
        srow[tid][0] = mean;
        srow[tid][1] = rsqrtf(var + LNEPS);
    }

    unsigned long long w2[16];
    load_weights_half(kern, poly, h, i, kh, w2);
    float si = scale[i];

    int fbase = h * (I_ * K_) + i * K_ + kh * 4;
    const float4 g0 = *reinterpret_cast<const float4*>(gamma + fbase);
    const float4 b0 = *reinterpret_cast<const float4*>(beta + fbase);

    __syncthreads();

    const float* xrow = x + (size_t)row0 * I_ + i;
    float* obase = out + (size_t)row0 * F_ + fbase;
    float xv = xrow[0];

#pragma unroll 1
    for (int r = 0; r < RB_; r++) {
        int rn = (r + 1 < RB_) ? r + 1 : r;
        float xv_next = xrow[(size_t)rn * I_];   // prefetch next row
        float mean = srow[r][0], rstd = srow[r][1];
        float xs = xv * si;
        float z[4];
        compute_z_half(xs, w2, z);
        float s[4];
#pragma unroll
        for (int k = 0; k < 4; k++) s[k] = (silu_f(z[k]) - mean) * rstd;

        stg_cs_128(obase + (size_t)r * F_,
                   fmaf(s[0], g0.x, b0.x), fmaf(s[1], g0.y, b0.y),
                   fmaf(s[2], g0.z, b0.z), fmaf(s[3], g0.w, b0.w));
        xv = xv_next;
    }
}

extern "C" void kernel_launch(void* const* d_in, const int* in_sizes, int n_in,
                              void* d_out, int out_size) {
    const float* x     = (const float*)d_in[0];
    const float* scale = (const float*)d_in[1];
    const float* poly  = (const float*)d_in[2];
    const float* kern  = (const float*)d_in[3];
    const float* gamma = (const float*)d_in[4];
    const float* beta  = (const float*)d_in[5];
    float* out = (float*)d_out;

    dim3 grid(FB_, RBLK_);
    k_stats<<<grid, NT_>>>(x, scale, poly, kern);
    k_out<<<grid, NT_>>>(x, scale, poly, kern, gamma, beta, out);
}

// round 13
// speedup vs baseline: 1.9459x; 1.0699x over previous
#include <cuda_runtime.h>

// ChebyshevEncoder: x*scale -> Chebyshev T0..T7 -> per-(h,i) 8x8 matmul -> *poly
// -> silu -> flatten [b, h*i*k] -> LayerNorm over 16384 features.
//
// Two-kernel recompute + k-split + coalesced lane remap (R12-measured: 127.3us,
// k_out 104.4us latency-bound: occ 34.3%, issue 34.8%, all pipes ~30%).
// R13: silu via tanh.approx (1 MUFU vs 2, dep chain 45->28 cyc; exact in
// saturation so large elements are error-free) + fully packed f32x2 silu and
// LN epilogue (z stays packed from dot accumulators to the store).

#define B_    4096
#define I_    512
#define M_    8
#define H_    4
#define K_    8
#define F_    16384      // H_*I_*K_
#define FB_   16         // feature (i) blocks
#define IC_   32         // i per block  (FB_*IC_ == I_)
#define RB_   32         // rows per CTA
#define RBLK_ 128        // row blocks   (RB_*RBLK_ == B_)
#define NT_   256        // 8 warps: warp=(h,ihalf), lane=(isub,kh)
#define LNEPS 1e-5f

typedef unsigned long long u64;

// per-row, per-featureblock partial [sum, sumsq]
__device__ float g_part[B_][FB_][2];

static __device__ __forceinline__ u64 pack2(float lo, float hi) {
    u64 r;
    asm("mov.b64 %0, {%1, %2};" : "=l"(r) : "f"(lo), "f"(hi));
    return r;
}
static __device__ __forceinline__ void unpack2(u64 v, float& lo, float& hi) {
    asm("mov.b64 {%0, %1}, %2;" : "=f"(lo), "=f"(hi) : "l"(v));
}
static __device__ __forceinline__ u64 ffma2(u64 a, u64 b, u64 c) {
    u64 d;
    asm("fma.rn.f32x2 %0, %1, %2, %3;" : "=l"(d) : "l"(a), "l"(b), "l"(c));
    return d;
}
static __device__ __forceinline__ u64 mul2(u64 a, u64 b) {
    u64 d;
    asm("mul.rn.f32x2 %0, %1, %2;" : "=l"(d) : "l"(a), "l"(b));
    return d;
}
static __device__ __forceinline__ u64 add2(u64 a, u64 b) {
    u64 d;
    asm("add.rn.f32x2 %0, %1, %2;" : "=l"(d) : "l"(a), "l"(b));
    return d;
}
static __device__ __forceinline__ float tanh_f(float x) {
    float r;
    asm("tanh.approx.f32 %0, %1;" : "=f"(r) : "f"(x));
    return r;
}

// Packed silu on a f32x2 pair: s = z * (0.5*tanh(0.5*z) + 0.5).
// tanh.approx saturates exactly to +-1 -> silu exact for large |z|;
// mid-range abs err <= ~2e-3 pre-LN, ~1e-4 after row normalization.
static __device__ __forceinline__ u64 silu2(u64 z2) {
    const u64 HALF2 = 0x3f0000003f000000ULL;  // (0.5f, 0.5f)
    u64 hz = mul2(z2, HALF2);
    float a, b;
    unpack2(hz, a, b);
    u64 th = pack2(tanh_f(a), tanh_f(b));
    u64 sg = ffma2(th, HALF2, HALF2);
    return mul2(z2, sg);
}

// Streaming 16B store (write-once output; evict-first in L2).
static __device__ __forceinline__ void stg_cs_128(float* p, float a, float b,
                                                  float c, float d) {
    asm volatile("st.global.cs.v4.f32 [%0], {%1, %2, %3, %4};"
                 :: "l"(p), "f"(a), "f"(b), "f"(c), "f"(d) : "memory");
}

// Load this thread's 8x4 weight half-slice (poly pre-folded) as 16 packed f32x2.
static __device__ __forceinline__ void load_weights_half(
        const float* __restrict__ kern, const float* __restrict__ poly,
        int h, int i, int kh, u64* w2) {
    const float* wbase = kern + ((size_t)(h * I_ + i) * M_) * K_ + kh * 4;
    const float4 p = *reinterpret_cast<const float4*>(
        poly + (size_t)(h * I_ + i) * K_ + kh * 4);
#pragma unroll
    for (int m = 0; m < M_; m++) {
        float4 a = *reinterpret_cast<const float4*>(wbase + (size_t)m * K_);
        w2[2 * m + 0] = pack2(a.x * p.x, a.y * p.y);
        w2[2 * m + 1] = pack2(a.z * p.z, a.w * p.w);
    }
}

// Chebyshev recurrence + packed 4-term-wide dot -> two packed z pairs.
static __device__ __forceinline__ void compute_z2(
        float xs, const u64* w2, u64& a0, u64& a1) {
    float c[M_];
    c[0] = 1.0f;                       // recurrence reads c[0]
    c[1] = xs;
    float t2 = xs + xs;
#pragma unroll
    for (int n = 2; n < M_; n++) c[n] = fmaf(t2, c[n - 1], -c[n - 2]);

    a0 = w2[0];
    a1 = w2[1];                        // m=0 term: c[0]==1
#pragma unroll
    for (int m = 1; m < M_; m++) {
        u64 cm = pack2(c[m], c[m]);
        a0 = ffma2(cm, w2[2 * m + 0], a0);
        a1 = ffma2(cm, w2[2 * m + 1], a1);
    }
}

// Thread decomposition shared by both kernels:
//   warp w = tid>>5:  h = w>>1, ihalf = w&1
//   lane:             kh = lane&1, isub = lane>>1
//   i = fb*IC_ + ihalf*16 + isub
// -> k_out stores from consecutive lanes are contiguous 16B chunks.

__global__ void __launch_bounds__(NT_, 3) k_stats(
        const float* __restrict__ x, const float* __restrict__ scale,
        const float* __restrict__ poly, const float* __restrict__ kern) {
    __shared__ float wacc[RB_][8][2];  // per-row, per-warp partials

    int tid = threadIdx.x;
    int lane = tid & 31, wid = tid >> 5;
    int h = wid >> 1, ihalf = wid & 1;
    int kh = lane & 1, isub = lane >> 1;
    int fb = blockIdx.x;               // fb-major grid
    int i = fb * IC_ + ihalf * 16 + isub;
    int row0 = blockIdx.y * RB_;

    u64 w2[16];
    load_weights_half(kern, poly, h, i, kh, w2);
    float si = scale[i];

    const float* xrow = x + (size_t)row0 * I_ + i;
    float xv = xrow[0];

#pragma unroll 1
    for (int r = 0; r < RB_; r++) {
        int rn = (r + 1 < RB_) ? r + 1 : r;
        float xv_next = xrow[(size_t)rn * I_];   // prefetch next row
        float xs = xv * si;
        u64 a0, a1;
        compute_z2(xs, w2, a0, a1);
        u64 s0 = silu2(a0), s1 = silu2(a1);
        u64 sp = add2(s0, s1);
        u64 qp = ffma2(s1, s1, mul2(s0, s0));
        float slo, shi, qlo, qhi;
        unpack2(sp, slo, shi);
        unpack2(qp, qlo, qhi);
        float sum = slo + shi, sq = qlo + qhi;
#pragma unroll
        for (int off = 16; off; off >>= 1) {
            sum += __shfl_xor_sync(0xffffffffu, sum, off);
            sq  += __shfl_xor_sync(0xffffffffu, sq, off);
        }
        if (lane == 0) {
            wacc[r][wid][0] = sum;
            wacc[r][wid][1] = sq;
        }
        xv = xv_next;
    }
    __syncthreads();
    if (tid < RB_ * 2) {
        int r = tid >> 1, comp = tid & 1;
        float v = 0.0f;
#pragma unroll
        for (int w = 0; w < 8; w++) v += wacc[r][w][comp];
        g_part[row0 + r][fb][comp] = v;
    }
}

__global__ void __launch_bounds__(NT_, 3) k_out(
        const float* __restrict__ x, const float* __restrict__ scale,
        const float* __restrict__ poly, const float* __restrict__ kern,
        const float* __restrict__ gamma, const float* __restrict__ beta,
        float* __restrict__ out) {
    __shared__ float srow[RB_][2];  // mean, rstd per row

    int tid = threadIdx.x;
    int lane = tid & 31, wid = tid >> 5;
    int h = wid >> 1, ihalf = wid & 1;
    int kh = lane & 1, isub = lane >> 1;
    int fb = blockIdx.x;               // fb-major grid
    int i = fb * IC_ + ihalf * 16 + isub;
    int row0 = blockIdx.y * RB_;

    if (tid < RB_) {
        float sum = 0.0f, sq = 0.0f;
#pragma unroll
        for (int f = 0; f < FB_; f++) {
            sum += g_part[row0 + tid][f][0];
            sq  += g_part[row0 + tid][f][1];
        }
        float mean = sum * (1.0f / F_);
        float var = fmaf(-mean, mean, sq * (1.0f / F_));  // biased variance
        srow[tid][0] = mean;
        srow[tid][1] = rsqrtf(var + LNEPS);
    }

    u64 w2[16];
    load_weights_half(kern, poly, h, i, kh, w2);
    float si = scale[i];

    int fbase = h * (I_ * K_) + i * K_ + kh * 4;
    const float4 g0 = *reinterpret_cast<const float4*>(gamma + fbase);
    const float4 b0 = *reinterpret_cast<const float4*>(beta + fbase);
    u64 gp0 = pack2(g0.x, g0.y), gp1 = pack2(g0.z, g0.w);
    u64 bp0 = pack2(b0.x, b0.y), bp1 = pack2(b0.z, b0.w);

    __syncthreads();

    const float* xrow = x + (size_t)row0 * I_ + i;
    float* obase = out + (size_t)row0 * F_ + fbase;
    float xv = xrow[0];

#pragma unroll 1
    for (int r = 0; r < RB_; r++) {
        int rn = (r + 1 < RB_) ? r + 1 : r;
        float xv_next = xrow[(size_t)rn * I_];   // prefetch next row
        float mean = srow[r][0], rstd = srow[r][1];
        u64 nm = pack2(-mean, -mean);
        u64 rs = pack2(rstd, rstd);
        float xs = xv * si;
        u64 a0, a1;
        compute_z2(xs, w2, a0, a1);
        u64 s0 = silu2(a0), s1 = silu2(a1);
        // o = ((s - mean) * rstd) * gamma + beta, all packed
        u64 o0 = ffma2(mul2(add2(s0, nm), rs), gp0, bp0);
        u64 o1 = ffma2(mul2(add2(s1, nm), rs), gp1, bp1);
        float ox, oy, oz, ow;
        unpack2(o0, ox, oy);
        unpack2(o1, oz, ow);
        stg_cs_128(obase + (size_t)r * F_, ox, oy, oz, ow);
        xv = xv_next;
    }
}

extern "C" void kernel_launch(void* const* d_in, const int* in_sizes, int n_in,
                              void* d_out, int out_size) {
    const float* x     = (const float*)d_in[0];
    const float* scale = (const float*)d_in[1];
    const float* poly  = (const float*)d_in[2];
    const float* kern  = (const float*)d_in[3];
    const float* gamma = (const float*)d_in[4];
    const float* beta  = (const float*)d_in[5];
    float* out = (float*)d_out;

    dim3 grid(FB_, RBLK_);
    k_stats<<<grid, NT_>>>(x, scale, poly, kern);
    k_out<<<grid, NT_>>>(x, scale, poly, kern, gamma, beta, out);
}